// round 1
// baseline (speedup 1.0000x reference)
#include <cuda_runtime.h>
#include <math.h>

// ---------------- problem constants ----------------
#define Bg   32
#define NPG  2048
#define Nn   (Bg*NPG)        // 65536
#define Ee   (Nn*8)          // 524288
#define IND  64
#define H1   128
#define H2   256
#define K1   1024
#define K2   512
#define N1   (Bg*K1)         // 32768
#define N2   (Bg*K2)         // 16384

// ---------------- scratch (device globals; no allocs) ----------------
__device__ float g_agg1 [Nn*IND];     // 16MB
__device__ float g_cnt1 [Nn];
__device__ float g_sseg1[Nn];
__device__ float g_rrel1[Nn];
__device__ float g_rroot1[Nn];
__device__ float g_pre1 [Nn*H1];      // 32MB (pre-act, then h1 in-place)
__device__ int   g_map1 [Nn];
__device__ int   g_perm1[N1];
__device__ float g_tanh1[N1];
__device__ int   g_src2 [Ee];
__device__ int   g_tgt2 [Ee];
__device__ float g_h1new[N1*H1];      // 16MB
__device__ float g_agg2 [N1*H1];      // 16MB
__device__ float g_cnt2 [N1];
__device__ float g_sseg2[N1];
__device__ float g_rrel2[N1];
__device__ float g_rroot2[N1];
__device__ float g_pre2 [N1*H2];      // 32MB (pre-act, then h2 in-place)
__device__ int   g_perm2[N2];
__device__ float g_tanh2[N2];
__device__ float g_bnacc[2*H2];

// ---------------- kernels ----------------

// mean/sum aggregation over edges: one thread per (edge, feature)
template<int D>
__global__ void agg_kernel(const int* __restrict__ src, const int* __restrict__ tgt,
                           const float* __restrict__ xin, float* __restrict__ aggo,
                           float* __restrict__ cnt, int nedges)
{
    int i = blockIdx.x * blockDim.x + threadIdx.x;
    if (i >= nedges * D) return;
    int e = i / D;
    int f = i - e * D;
    int s = src[e];
    if (s < 0) return;
    int t = tgt[e];
    atomicAdd(&aggo[t*D + f], xin[s*D + f]);
    if (f == 0) atomicAdd(&cnt[t], 1.0f);
}

// pre[n,OD] = (agg[n,:]/max(cnt,1)) @ Wl + xin @ Wr + bias
template<int KD, int OD>
__global__ void gemm_dual(const float* __restrict__ agg, const float* __restrict__ cnt,
                          const float* __restrict__ xin,
                          const float* __restrict__ Wl, const float* __restrict__ Wr,
                          const float* __restrict__ bias, float* __restrict__ outp)
{
    const int TK = 32, RB = 32, CT = 16, CPT = OD / CT;
    extern __shared__ float sh[];
    float* sWl = sh;                     // TK*OD
    float* sWr = sWl + TK*OD;            // TK*OD
    float* sA  = sWr + TK*OD;            // RB*TK (mean)
    float* sB  = sA  + RB*TK;            // RB*TK (root input)

    int tid  = threadIdx.x;              // 256
    int ct   = tid & 15;
    int rt   = tid >> 4;                 // 0..15 -> rows 2rt, 2rt+1
    int row0 = blockIdx.x * RB;

    float acc0[CPT], acc1[CPT];
#pragma unroll
    for (int j = 0; j < CPT; j++) { acc0[j] = 0.f; acc1[j] = 0.f; }

    for (int kt = 0; kt < KD; kt += TK) {
        for (int i = tid; i < TK*OD; i += 256) {
            sWl[i] = Wl[kt*OD + i];      // W row-major [KD,OD] -> contiguous
            sWr[i] = Wr[kt*OD + i];
        }
        for (int i = tid; i < RB*TK; i += 256) {
            int rr = i >> 5;
            int kk = i & 31;
            int row = row0 + rr;
            float inv = 1.f / fmaxf(cnt[row], 1.f);
            sA[i] = agg[row*KD + kt + kk] * inv;
            sB[i] = xin[row*KD + kt + kk];
        }
        __syncthreads();
#pragma unroll
        for (int kk = 0; kk < TK; kk++) {
            float a0 = sA[(2*rt  )*TK + kk];
            float a1 = sA[(2*rt+1)*TK + kk];
            float b0 = sB[(2*rt  )*TK + kk];
            float b1 = sB[(2*rt+1)*TK + kk];
#pragma unroll
            for (int j = 0; j < CPT; j++) {
                float wl = sWl[kk*OD + j*CT + ct];
                float wr = sWr[kk*OD + j*CT + ct];
                acc0[j] += a0*wl + b0*wr;
                acc1[j] += a1*wl + b1*wr;
            }
        }
        __syncthreads();
    }
    int r0 = row0 + 2*rt, r1 = r0 + 1;
#pragma unroll
    for (int j = 0; j < CPT; j++) {
        int col = j*CT + ct;
        float bb = bias[col];
        outp[r0*OD + col] = acc0[j] + bb;
        outp[r1*OD + col] = acc1[j] + bb;
    }
}

// column sums + sumsq (for BatchNorm), blockDim = D
template<int D>
__global__ void bnstats_kernel(const float* __restrict__ pre, float* __restrict__ acc, int nrows)
{
    int c = threadIdx.x;
    int chunk = nrows / gridDim.x;
    int r0 = blockIdx.x * chunk;
    float s = 0.f, s2 = 0.f;
    for (int r = r0; r < r0 + chunk; r++) {
        float v = pre[r*D + c];
        s += v; s2 += v*v;
    }
    atomicAdd(&acc[c], s);
    atomicAdd(&acc[D + c], s2);
}

// in-place BN + ReLU
template<int D>
__global__ void bnapply_kernel(float* __restrict__ pre, const float* __restrict__ acc,
                               const float* __restrict__ g, const float* __restrict__ b, int nrows)
{
    int i = blockIdx.x * blockDim.x + threadIdx.x;
    if (i >= nrows * D) return;
    int c = i & (D - 1);
    float invn = 1.f / (float)nrows;
    float m   = acc[c] * invn;
    float var = acc[D + c] * invn - m*m;
    float sc  = rsqrtf(var + 1e-5f) * g[c];
    float v   = (pre[i] - m) * sc + b[c];
    pre[i] = fmaxf(v, 0.f);
}

// two D-dim dot products per node (warp per node)
template<int D>
__global__ void dots_kernel(const float* __restrict__ h, const float* __restrict__ wrel,
                            const float* __restrict__ wroot,
                            float* __restrict__ rrel, float* __restrict__ rroot, int n)
{
    int w = (blockIdx.x * blockDim.x + threadIdx.x) >> 5;
    int lane = threadIdx.x & 31;
    if (w >= n) return;
    float s1 = 0.f, s2 = 0.f;
#pragma unroll
    for (int t = lane; t < D; t += 32) {
        float v = h[w*D + t];
        s1 += v * wrel[t];
        s2 += v * wroot[t];
    }
#pragma unroll
    for (int o = 16; o; o >>= 1) {
        s1 += __shfl_down_sync(0xFFFFFFFFu, s1, o);
        s2 += __shfl_down_sync(0xFFFFFFFFu, s2, o);
    }
    if (lane == 0) { rrel[w] = s1; rroot[w] = s2; }
}

// scalar segment-sum of rrel[src] into sseg[tgt]
__global__ void escore_kernel(const int* __restrict__ src, const int* __restrict__ tgt,
                              const float* __restrict__ rrel, float* __restrict__ sseg, int nedges)
{
    int e = blockIdx.x * blockDim.x + threadIdx.x;
    if (e >= nedges) return;
    int s = src[e];
    if (s < 0) return;
    atomicAdd(&sseg[tgt[e]], rrel[s]);
}

// per-graph top-K via bitonic sort of (score,idx) keys; set-invariant ordering
template<int NPGT, int KSEL>
__global__ void topk_kernel(const float* __restrict__ sseg, const float* __restrict__ rroot,
                            const float* __restrict__ brel,
                            int* __restrict__ perm, float* __restrict__ tanhv,
                            int* __restrict__ mapping)
{
    __shared__ unsigned long long keys[NPGT];
    int g = blockIdx.x, tid = threadIdx.x;
    float br = brel[0];
    for (int i = tid; i < NPGT; i += blockDim.x) {
        int node = g*NPGT + i;
        float sc = sseg[node] + br + rroot[node];
        unsigned u = __float_as_uint(sc);
        u = (u & 0x80000000u) ? ~u : (u | 0x80000000u);   // order-preserving map
        keys[i] = ((unsigned long long)u << 32) | (unsigned)i;
    }
    __syncthreads();
    for (int k = 2; k <= NPGT; k <<= 1) {
        for (int j = k >> 1; j > 0; j >>= 1) {
            for (int t = tid; t < NPGT; t += blockDim.x) {
                int ixj = t ^ j;
                if (ixj > t) {
                    unsigned long long a = keys[t], c = keys[ixj];
                    bool desc = ((t & k) == 0);
                    if ((a < c) == desc) { keys[t] = c; keys[ixj] = a; }
                }
            }
            __syncthreads();
        }
    }
    for (int t = tid; t < KSEL; t += blockDim.x) {
        int li = (int)(keys[t] & 0xFFFFFFFFull);
        int node = g*NPGT + li;
        float sc = sseg[node] + br + rroot[node];
        int ni = g*KSEL + t;
        perm[ni]  = node;
        tanhv[ni] = tanhf(sc);
        if (mapping) mapping[node] = ni;
    }
}

// gather + tanh-scale (float4)
__global__ void gather_kernel(const float* __restrict__ h, const int* __restrict__ perm,
                              const float* __restrict__ tv, float* __restrict__ o, int n)
{
    const int V = H1 / 4;  // 32
    int i = blockIdx.x * blockDim.x + threadIdx.x;
    if (i >= n * V) return;
    int node = i / V, off = i - node * V;
    float4 v = reinterpret_cast<const float4*>(h)[(long)perm[node]*V + off];
    float t = tv[node];
    v.x *= t; v.y *= t; v.z *= t; v.w *= t;
    reinterpret_cast<float4*>(o)[i] = v;
}

__global__ void remap_kernel(const int* __restrict__ src, const int* __restrict__ tgt,
                             const int* __restrict__ mapping,
                             int* __restrict__ src2, int* __restrict__ tgt2)
{
    int e = blockIdx.x * blockDim.x + threadIdx.x;
    if (e >= Ee) return;
    int s = mapping[src[e]];
    int t = mapping[tgt[e]];
    if (s < 0 || t < 0) { s = -1; t = -1; }
    src2[e] = s; tgt2[e] = t;
}

// per-graph: pooled mean -> relu -> 256x2 linear -> softmax
__global__ void final_kernel(const float* __restrict__ h2, const int* __restrict__ perm2,
                             const float* __restrict__ tanhv2, const float* __restrict__ Wlin,
                             const float* __restrict__ blin, float* __restrict__ outp)
{
    int g = blockIdx.x, c = threadIdx.x;   // 256 threads
    __shared__ int   sp[K2];
    __shared__ float st[K2];
    for (int i = c; i < K2; i += 256) { sp[i] = perm2[g*K2 + i]; st[i] = tanhv2[g*K2 + i]; }
    __syncthreads();
    float acc = 0.f;
    for (int r = 0; r < K2; r++)
        acc += h2[(long)sp[r]*H2 + c] * st[r];
    float p = fmaxf(acc * (1.0f / (float)K2), 0.f);
    __shared__ float red0[256], red1[256];
    red0[c] = p * Wlin[c*2 + 0];
    red1[c] = p * Wlin[c*2 + 1];
    __syncthreads();
    for (int s = 128; s; s >>= 1) {
        if (c < s) { red0[c] += red0[c+s]; red1[c] += red1[c+s]; }
        __syncthreads();
    }
    if (c == 0) {
        float a = red0[0] + blin[0];
        float b = red1[0] + blin[1];
        float m = fmaxf(a, b);
        float ea = expf(a - m), eb = expf(b - m);
        float inv = 1.f / (ea + eb);
        outp[g*2 + 0] = ea * inv;
        outp[g*2 + 1] = eb * inv;
    }
}

// ---------------- host launch ----------------
template <typename T>
static void* symaddr(const T& s) { void* p = nullptr; cudaGetSymbolAddress(&p, s); return p; }

extern "C" void kernel_launch(void* const* d_in, const int* in_sizes, int n_in,
                              void* d_out, int out_size)
{
    const float* x     = (const float*)d_in[0];
    const int*   ei    = (const int*)  d_in[1];
    const int*   src   = ei;
    const int*   tgt   = ei + Ee;
    // d_in[2] = batch (structure known statically)
    const float* W1l   = (const float*)d_in[3];
    const float* b1l   = (const float*)d_in[4];
    const float* W1r   = (const float*)d_in[5];
    const float* bn1g  = (const float*)d_in[6];
    const float* bn1b  = (const float*)d_in[7];
    const float* p1Wrel  = (const float*)d_in[8];
    const float* p1brel  = (const float*)d_in[9];
    const float* p1Wroot = (const float*)d_in[10];
    const float* W2l   = (const float*)d_in[11];
    const float* b2l   = (const float*)d_in[12];
    const float* W2r   = (const float*)d_in[13];
    const float* bn2g  = (const float*)d_in[14];
    const float* bn2b  = (const float*)d_in[15];
    const float* p2Wrel  = (const float*)d_in[16];
    const float* p2brel  = (const float*)d_in[17];
    const float* p2Wroot = (const float*)d_in[18];
    const float* Wlin  = (const float*)d_in[19];
    const float* blin  = (const float*)d_in[20];
    float* out = (float*)d_out;

    float* agg1  = (float*)symaddr(g_agg1);
    float* cnt1  = (float*)symaddr(g_cnt1);
    float* sseg1 = (float*)symaddr(g_sseg1);
    float* rrel1 = (float*)symaddr(g_rrel1);
    float* rroot1= (float*)symaddr(g_rroot1);
    float* pre1  = (float*)symaddr(g_pre1);
    int*   map1  = (int*)  symaddr(g_map1);
    int*   perm1 = (int*)  symaddr(g_perm1);
    float* tanh1 = (float*)symaddr(g_tanh1);
    int*   src2  = (int*)  symaddr(g_src2);
    int*   tgt2  = (int*)  symaddr(g_tgt2);
    float* h1new = (float*)symaddr(g_h1new);
    float* agg2  = (float*)symaddr(g_agg2);
    float* cnt2  = (float*)symaddr(g_cnt2);
    float* sseg2 = (float*)symaddr(g_sseg2);
    float* rrel2 = (float*)symaddr(g_rrel2);
    float* rroot2= (float*)symaddr(g_rroot2);
    float* pre2  = (float*)symaddr(g_pre2);
    int*   perm2 = (int*)  symaddr(g_perm2);
    float* tanh2 = (float*)symaddr(g_tanh2);
    float* bnacc = (float*)symaddr(g_bnacc);

    cudaFuncSetAttribute(reinterpret_cast<const void*>(gemm_dual<H1, H2>),
                         cudaFuncAttributeMaxDynamicSharedMemorySize, 73728);

    // ---- stage 1 ----
    cudaMemsetAsync(agg1,  0, sizeof(float)*Nn*IND);
    cudaMemsetAsync(cnt1,  0, sizeof(float)*Nn);
    cudaMemsetAsync(sseg1, 0, sizeof(float)*Nn);
    cudaMemsetAsync(bnacc, 0, sizeof(float)*2*H2);
    cudaMemsetAsync(map1, 0xFF, sizeof(int)*Nn);   // -1

    agg_kernel<IND><<<(Ee*IND)/256, 256>>>(src, tgt, x, agg1, cnt1, Ee);
    {
        int smem = (2*32*H1 + 2*32*32) * 4;   // 40960
        gemm_dual<IND, H1><<<Nn/32, 256, smem>>>(agg1, cnt1, x, W1l, W1r, b1l, pre1);
    }
    bnstats_kernel<H1><<<128, H1>>>(pre1, bnacc, Nn);
    bnapply_kernel<H1><<<(Nn*H1)/256, 256>>>(pre1, bnacc, bn1g, bn1b, Nn);
    dots_kernel<H1><<<Nn/8, 256>>>(pre1, p1Wrel, p1Wroot, rrel1, rroot1, Nn);
    escore_kernel<<<Ee/256, 256>>>(src, tgt, rrel1, sseg1, Ee);
    topk_kernel<NPG, K1><<<Bg, 1024>>>(sseg1, rroot1, p1brel, perm1, tanh1, map1);
    gather_kernel<<<(N1*(H1/4))/256, 256>>>(pre1, perm1, tanh1, h1new, N1);
    remap_kernel<<<Ee/256, 256>>>(src, tgt, map1, src2, tgt2);

    // ---- stage 2 ----
    cudaMemsetAsync(agg2,  0, sizeof(float)*N1*H1);
    cudaMemsetAsync(cnt2,  0, sizeof(float)*N1);
    cudaMemsetAsync(sseg2, 0, sizeof(float)*N1);
    cudaMemsetAsync(bnacc, 0, sizeof(float)*2*H2);

    agg_kernel<H1><<<(Ee*H1)/256, 256>>>(src2, tgt2, h1new, agg2, cnt2, Ee);
    {
        int smem = (2*32*H2 + 2*32*32) * 4;   // 73728
        gemm_dual<H1, H2><<<N1/32, 256, smem>>>(agg2, cnt2, h1new, W2l, W2r, b2l, pre2);
    }
    bnstats_kernel<H2><<<128, H2>>>(pre2, bnacc, N1);
    bnapply_kernel<H2><<<(N1*H2)/256, 256>>>(pre2, bnacc, bn2g, bn2b, N1);
    dots_kernel<H2><<<N1/8, 256>>>(pre2, p2Wrel, p2Wroot, rrel2, rroot2, N1);
    escore_kernel<<<Ee/256, 256>>>(src2, tgt2, rrel2, sseg2, Ee);
    topk_kernel<K1, K2><<<Bg, 1024>>>(sseg2, rroot2, p2brel, perm2, tanh2, nullptr);

    // ---- readout ----
    final_kernel<<<Bg, 256>>>(pre2, perm2, tanh2, Wlin, blin, out);

    (void)in_sizes; (void)n_in; (void)out_size;
}

// round 2
// speedup vs baseline: 1.4230x; 1.4230x over previous
#include <cuda_runtime.h>
#include <math.h>

// ---------------- problem constants ----------------
#define Bg   32
#define NPG  2048
#define Nn   (Bg*NPG)        // 65536
#define Ee   (Nn*8)          // 524288
#define IND  64
#define H1   128
#define H2   256
#define K1   1024
#define K2   512
#define N1   (Bg*K1)         // 32768
#define N2   (Bg*K2)         // 16384

// ---------------- scratch (device globals; no allocs) ----------------
__device__ float g_agg1 [Nn*IND];
__device__ float g_cnt1 [Nn];
__device__ float g_sseg1[Nn];
__device__ float g_rrel1[Nn];
__device__ float g_rroot1[Nn];
__device__ float g_pre1 [Nn*H1];
__device__ int   g_map1 [Nn];
__device__ int   g_perm1[N1];
__device__ float g_tanh1[N1];
__device__ int   g_src2 [Ee];
__device__ int   g_tgt2 [Ee];
__device__ float g_h1new[N1*H1];
__device__ float g_agg2 [N1*H1];
__device__ float g_cnt2 [N1];
__device__ float g_sseg2[N1];
__device__ float g_rrel2[N1];
__device__ float g_rroot2[N1];
__device__ float g_pre2 [N1*H2];
__device__ int   g_perm2[N2];
__device__ float g_tanh2[N2];
__device__ float g_bnacc[2*H2];
__device__ float g_scale[H2];
__device__ float g_shift[H2];

// ---------------- f32x2 helpers ----------------
__device__ __forceinline__ unsigned long long pk2(float lo, float hi) {
    unsigned long long r;
    asm("mov.b64 %0, {%1,%2};" : "=l"(r) : "f"(lo), "f"(hi));
    return r;
}
__device__ __forceinline__ void upk2(unsigned long long v, float& lo, float& hi) {
    asm("mov.b64 {%0,%1}, %2;" : "=f"(lo), "=f"(hi) : "l"(v));
}
__device__ __forceinline__ void ffma2(unsigned long long& d, unsigned long long a, unsigned long long b) {
    asm("fma.rn.f32x2 %0, %1, %2, %0;" : "+l"(d) : "l"(a), "l"(b));
}

// ---------------- kernels ----------------

// vectorized mean aggregation over edges: one thread per (edge, float4)
template<int D>
__global__ void agg_kernel(const int* __restrict__ src, const int* __restrict__ tgt,
                           const float* __restrict__ xin, float* __restrict__ aggo,
                           float* __restrict__ cnt, int nedges)
{
    const int V = D / 4;
    int i = blockIdx.x * blockDim.x + threadIdx.x;
    if (i >= nedges * V) return;
    int e  = i / V;
    int f4 = i - e * V;
    int s = src[e];
    if (s < 0) return;
    int t = tgt[e];
    float4 v = reinterpret_cast<const float4*>(xin)[(size_t)s * V + f4];
    asm volatile("red.global.add.v4.f32 [%0], {%1,%2,%3,%4};"
                 :: "l"(&aggo[(size_t)t * D + f4 * 4]),
                    "f"(v.x), "f"(v.y), "f"(v.z), "f"(v.w) : "memory");
    if (f4 == 0) atomicAdd(&cnt[t], 1.0f);
}

// pre[n,OD] = (agg[n]/max(cnt,1)) @ Wl + xin @ Wr + bias   (K concat, FFMA2)
// 256 threads; CG column-groups of TN cols; RPT=8 rows per thread (as 4 row-pairs).
template<int KD, int OD, int BM, int TN, int CG>
__global__ void gemm_dual2(const float* __restrict__ agg, const float* __restrict__ cnt,
                           const float* __restrict__ xin,
                           const float* __restrict__ Wl, const float* __restrict__ Wr,
                           const float* __restrict__ bias, float* __restrict__ outp)
{
    const int BK = 32, ASTR = BM + 4;
    extern __shared__ float sh[];
    float* sW = sh;             // BK*OD
    float* sA = sh + BK * OD;   // BK*ASTR

    int tid = threadIdx.x;
    int tx  = tid % CG;         // column group
    int ty  = tid / CG;         // row group (8 rows)
    int row0 = blockIdx.x * BM;

    unsigned long long acc[4][TN];
#pragma unroll
    for (int r = 0; r < 4; r++)
#pragma unroll
        for (int j = 0; j < TN; j++) acc[r][j] = 0ull;

    for (int kt = 0; kt < 2 * KD; kt += BK) {
        // stage W tile [BK x OD] (row-major, coalesced)
        for (int i = tid; i < BK * OD; i += 256) {
            int k = i / OD, c = i - k * OD;
            int kg = kt + k;
            sW[i] = (kg < KD) ? Wl[(size_t)kg * OD + c] : Wr[(size_t)(kg - KD) * OD + c];
        }
        // stage A tile transposed [BK x BM] (+4 pad), fold mean division
        for (int i = tid; i < BM * BK; i += 256) {
            int m = i >> 5, k = i & 31;
            int kg = kt + k;
            int row = row0 + m;
            float v;
            if (kg < KD) v = agg[(size_t)row * KD + kg] * (1.f / fmaxf(cnt[row], 1.f));
            else         v = xin[(size_t)row * KD + (kg - KD)];
            sA[k * ASTR + m] = v;
        }
        __syncthreads();
#pragma unroll
        for (int k = 0; k < BK; k++) {
            const float4 a0 = *reinterpret_cast<const float4*>(&sA[k * ASTR + ty * 8]);
            const float4 a1 = *reinterpret_cast<const float4*>(&sA[k * ASTR + ty * 8 + 4]);
            unsigned long long ap[4] = { pk2(a0.x, a0.y), pk2(a0.z, a0.w),
                                         pk2(a1.x, a1.y), pk2(a1.z, a1.w) };
#pragma unroll
            for (int jj = 0; jj < TN / 4; jj++) {
                float4 w4 = *reinterpret_cast<const float4*>(&sW[k * OD + tx * TN + jj * 4]);
                unsigned long long w0 = pk2(w4.x, w4.x), w1 = pk2(w4.y, w4.y);
                unsigned long long w2 = pk2(w4.z, w4.z), w3 = pk2(w4.w, w4.w);
#pragma unroll
                for (int r = 0; r < 4; r++) {
                    ffma2(acc[r][jj*4+0], ap[r], w0);
                    ffma2(acc[r][jj*4+1], ap[r], w1);
                    ffma2(acc[r][jj*4+2], ap[r], w2);
                    ffma2(acc[r][jj*4+3], ap[r], w3);
                }
            }
        }
        __syncthreads();
    }
    // epilogue: unpack, add bias, vector store
#pragma unroll
    for (int r = 0; r < 4; r++) {
        float lo[TN], hi[TN];
#pragma unroll
        for (int j = 0; j < TN; j++) upk2(acc[r][j], lo[j], hi[j]);
        int row_lo = row0 + ty * 8 + 2 * r;
#pragma unroll
        for (int jj = 0; jj < TN / 4; jj++) {
            int c = tx * TN + jj * 4;
            float4 bb = *reinterpret_cast<const float4*>(&bias[c]);
            float4 o0 = make_float4(lo[jj*4]+bb.x, lo[jj*4+1]+bb.y, lo[jj*4+2]+bb.z, lo[jj*4+3]+bb.w);
            float4 o1 = make_float4(hi[jj*4]+bb.x, hi[jj*4+1]+bb.y, hi[jj*4+2]+bb.z, hi[jj*4+3]+bb.w);
            *reinterpret_cast<float4*>(&outp[(size_t)row_lo * OD + c])       = o0;
            *reinterpret_cast<float4*>(&outp[(size_t)(row_lo + 1) * OD + c]) = o1;
        }
    }
}

// column sums + sumsq (for BatchNorm), blockDim = D
template<int D>
__global__ void bnstats_kernel(const float* __restrict__ pre, float* __restrict__ acc, int nrows)
{
    int c = threadIdx.x;
    int chunk = nrows / gridDim.x;
    int r0 = blockIdx.x * chunk;
    float s = 0.f, s2 = 0.f;
    for (int r = r0; r < r0 + chunk; r++) {
        float v = pre[(size_t)r * D + c];
        s += v; s2 += v * v;
    }
    atomicAdd(&acc[c], s);
    atomicAdd(&acc[D + c], s2);
}

// precompute BN scale/shift per column (1 block)
__global__ void bnfinal_kernel(const float* __restrict__ acc, const float* __restrict__ g,
                               const float* __restrict__ b, float* __restrict__ scale,
                               float* __restrict__ shift, int D, float invn)
{
    int c = threadIdx.x;
    if (c >= D) return;
    float m   = acc[c] * invn;
    float var = acc[D + c] * invn - m * m;
    float sc  = rsqrtf(var + 1e-5f) * g[c];
    scale[c] = sc;
    shift[c] = b[c] - m * sc;
}

// fused: BN apply + ReLU (in place) + two score dot products. One warp per row.
template<int D>
__global__ void bnad_kernel(float* __restrict__ pre, const float* __restrict__ scale,
                            const float* __restrict__ shift,
                            const float* __restrict__ wrel, const float* __restrict__ wroot,
                            float* __restrict__ rrel, float* __restrict__ rroot, int nrows)
{
    int w = (blockIdx.x * blockDim.x + threadIdx.x) >> 5;
    int lane = threadIdx.x & 31;
    if (w >= nrows) return;
    const int V = D / 128;   // float4 chunks per lane
    float s1 = 0.f, s2 = 0.f;
    float4* rowp = reinterpret_cast<float4*>(pre + (size_t)w * D);
#pragma unroll
    for (int q = 0; q < V; q++) {
        int c4 = lane + q * 32;
        float4 v  = rowp[c4];
        float4 sc = reinterpret_cast<const float4*>(scale)[c4];
        float4 sh = reinterpret_cast<const float4*>(shift)[c4];
        v.x = fmaxf(fmaf(v.x, sc.x, sh.x), 0.f);
        v.y = fmaxf(fmaf(v.y, sc.y, sh.y), 0.f);
        v.z = fmaxf(fmaf(v.z, sc.z, sh.z), 0.f);
        v.w = fmaxf(fmaf(v.w, sc.w, sh.w), 0.f);
        rowp[c4] = v;
        float4 wr = reinterpret_cast<const float4*>(wrel)[c4];
        float4 wo = reinterpret_cast<const float4*>(wroot)[c4];
        s1 += v.x*wr.x + v.y*wr.y + v.z*wr.z + v.w*wr.w;
        s2 += v.x*wo.x + v.y*wo.y + v.z*wo.z + v.w*wo.w;
    }
#pragma unroll
    for (int o = 16; o; o >>= 1) {
        s1 += __shfl_down_sync(0xFFFFFFFFu, s1, o);
        s2 += __shfl_down_sync(0xFFFFFFFFu, s2, o);
    }
    if (lane == 0) { rrel[w] = s1; rroot[w] = s2; }
}

// scalar segment-sum of rrel[src] into sseg[tgt]
__global__ void escore_kernel(const int* __restrict__ src, const int* __restrict__ tgt,
                              const float* __restrict__ rrel, float* __restrict__ sseg, int nedges)
{
    int e = blockIdx.x * blockDim.x + threadIdx.x;
    if (e >= nedges) return;
    int s = src[e];
    if (s < 0) return;
    atomicAdd(&sseg[tgt[e]], rrel[s]);
}

// per-graph top-K via bitonic sort of (score,idx) keys; set-invariant ordering
template<int NPGT, int KSEL>
__global__ void topk_kernel(const float* __restrict__ sseg, const float* __restrict__ rroot,
                            const float* __restrict__ brel,
                            int* __restrict__ perm, float* __restrict__ tanhv,
                            int* __restrict__ mapping)
{
    __shared__ unsigned long long keys[NPGT];
    int g = blockIdx.x, tid = threadIdx.x;
    float br = brel[0];
    for (int i = tid; i < NPGT; i += blockDim.x) {
        int node = g * NPGT + i;
        float sc = sseg[node] + br + rroot[node];
        unsigned u = __float_as_uint(sc);
        u = (u & 0x80000000u) ? ~u : (u | 0x80000000u);
        keys[i] = ((unsigned long long)u << 32) | (unsigned)i;
    }
    __syncthreads();
    for (int k = 2; k <= NPGT; k <<= 1) {
        for (int j = k >> 1; j > 0; j >>= 1) {
            for (int t = tid; t < NPGT; t += blockDim.x) {
                int ixj = t ^ j;
                if (ixj > t) {
                    unsigned long long a = keys[t], c = keys[ixj];
                    bool desc = ((t & k) == 0);
                    if ((a < c) == desc) { keys[t] = c; keys[ixj] = a; }
                }
            }
            __syncthreads();
        }
    }
    for (int t = tid; t < KSEL; t += blockDim.x) {
        int li = (int)(keys[t] & 0xFFFFFFFFull);
        int node = g * NPGT + li;
        float sc = sseg[node] + br + rroot[node];
        int ni = g * KSEL + t;
        perm[ni]  = node;
        tanhv[ni] = tanhf(sc);
        if (mapping) mapping[node] = ni;
    }
}

// gather + tanh-scale (float4)
__global__ void gather_kernel(const float* __restrict__ h, const int* __restrict__ perm,
                              const float* __restrict__ tv, float* __restrict__ o, int n)
{
    const int V = H1 / 4;  // 32
    int i = blockIdx.x * blockDim.x + threadIdx.x;
    if (i >= n * V) return;
    int node = i / V, off = i - node * V;
    float4 v = reinterpret_cast<const float4*>(h)[(size_t)perm[node] * V + off];
    float t = tv[node];
    v.x *= t; v.y *= t; v.z *= t; v.w *= t;
    reinterpret_cast<float4*>(o)[i] = v;
}

__global__ void remap_kernel(const int* __restrict__ src, const int* __restrict__ tgt,
                             const int* __restrict__ mapping,
                             int* __restrict__ src2, int* __restrict__ tgt2)
{
    int e = blockIdx.x * blockDim.x + threadIdx.x;
    if (e >= Ee) return;
    int s = mapping[src[e]];
    int t = mapping[tgt[e]];
    if (s < 0 || t < 0) { s = -1; t = -1; }
    src2[e] = s; tgt2[e] = t;
}

// per-graph: pooled mean -> relu -> 256x2 linear -> softmax
__global__ void final_kernel(const float* __restrict__ h2, const int* __restrict__ perm2,
                             const float* __restrict__ tanhv2, const float* __restrict__ Wlin,
                             const float* __restrict__ blin, float* __restrict__ outp)
{
    int g = blockIdx.x, c = threadIdx.x;   // 256 threads
    __shared__ int   sp[K2];
    __shared__ float st[K2];
    for (int i = c; i < K2; i += 256) { sp[i] = perm2[g * K2 + i]; st[i] = tanhv2[g * K2 + i]; }
    __syncthreads();
    float acc = 0.f;
#pragma unroll 4
    for (int r = 0; r < K2; r++)
        acc += h2[(size_t)sp[r] * H2 + c] * st[r];
    float p = fmaxf(acc * (1.0f / (float)K2), 0.f);
    __shared__ float red0[256], red1[256];
    red0[c] = p * Wlin[c * 2 + 0];
    red1[c] = p * Wlin[c * 2 + 1];
    __syncthreads();
    for (int s = 128; s; s >>= 1) {
        if (c < s) { red0[c] += red0[c + s]; red1[c] += red1[c + s]; }
        __syncthreads();
    }
    if (c == 0) {
        float a = red0[0] + blin[0];
        float b = red1[0] + blin[1];
        float m = fmaxf(a, b);
        float ea = expf(a - m), eb = expf(b - m);
        float inv = 1.f / (ea + eb);
        outp[g * 2 + 0] = ea * inv;
        outp[g * 2 + 1] = eb * inv;
    }
}

// ---------------- host launch ----------------
template <typename T>
static void* symaddr(const T& s) { void* p = nullptr; cudaGetSymbolAddress(&p, s); return p; }

extern "C" void kernel_launch(void* const* d_in, const int* in_sizes, int n_in,
                              void* d_out, int out_size)
{
    const float* x     = (const float*)d_in[0];
    const int*   ei    = (const int*)  d_in[1];
    const int*   src   = ei;
    const int*   tgt   = ei + Ee;
    const float* W1l   = (const float*)d_in[3];
    const float* b1l   = (const float*)d_in[4];
    const float* W1r   = (const float*)d_in[5];
    const float* bn1g  = (const float*)d_in[6];
    const float* bn1b  = (const float*)d_in[7];
    const float* p1Wrel  = (const float*)d_in[8];
    const float* p1brel  = (const float*)d_in[9];
    const float* p1Wroot = (const float*)d_in[10];
    const float* W2l   = (const float*)d_in[11];
    const float* b2l   = (const float*)d_in[12];
    const float* W2r   = (const float*)d_in[13];
    const float* bn2g  = (const float*)d_in[14];
    const float* bn2b  = (const float*)d_in[15];
    const float* p2Wrel  = (const float*)d_in[16];
    const float* p2brel  = (const float*)d_in[17];
    const float* p2Wroot = (const float*)d_in[18];
    const float* Wlin  = (const float*)d_in[19];
    const float* blin  = (const float*)d_in[20];
    float* out = (float*)d_out;

    float* agg1  = (float*)symaddr(g_agg1);
    float* cnt1  = (float*)symaddr(g_cnt1);
    float* sseg1 = (float*)symaddr(g_sseg1);
    float* rrel1 = (float*)symaddr(g_rrel1);
    float* rroot1= (float*)symaddr(g_rroot1);
    float* pre1  = (float*)symaddr(g_pre1);
    int*   map1  = (int*)  symaddr(g_map1);
    int*   perm1 = (int*)  symaddr(g_perm1);
    float* tanh1 = (float*)symaddr(g_tanh1);
    int*   src2  = (int*)  symaddr(g_src2);
    int*   tgt2  = (int*)  symaddr(g_tgt2);
    float* h1new = (float*)symaddr(g_h1new);
    float* agg2  = (float*)symaddr(g_agg2);
    float* cnt2  = (float*)symaddr(g_cnt2);
    float* sseg2 = (float*)symaddr(g_sseg2);
    float* rrel2 = (float*)symaddr(g_rrel2);
    float* rroot2= (float*)symaddr(g_rroot2);
    float* pre2  = (float*)symaddr(g_pre2);
    int*   perm2 = (int*)  symaddr(g_perm2);
    float* tanh2 = (float*)symaddr(g_tanh2);
    float* bnacc = (float*)symaddr(g_bnacc);
    float* scale = (float*)symaddr(g_scale);
    float* shift = (float*)symaddr(g_shift);

    // ---- stage 1 ----
    cudaMemsetAsync(agg1,  0, sizeof(float)*Nn*IND);
    cudaMemsetAsync(cnt1,  0, sizeof(float)*Nn);
    cudaMemsetAsync(sseg1, 0, sizeof(float)*Nn);
    cudaMemsetAsync(bnacc, 0, sizeof(float)*2*H2);
    cudaMemsetAsync(map1, 0xFF, sizeof(int)*Nn);   // -1

    agg_kernel<IND><<<(Ee*(IND/4))/256, 256>>>(src, tgt, x, agg1, cnt1, Ee);
    {
        // KD=64, OD=128, BM=128, TN=8, CG=16 ; smem = (32*128 + 32*132)*4 = 33280
        int smem = (32*H1 + 32*(128+4)) * 4;
        gemm_dual2<IND, H1, 128, 8, 16><<<Nn/128, 256, smem>>>(agg1, cnt1, x, W1l, W1r, b1l, pre1);
    }
    bnstats_kernel<H1><<<256, H1>>>(pre1, bnacc, Nn);
    bnfinal_kernel<<<1, H1>>>(bnacc, bn1g, bn1b, scale, shift, H1, 1.f/(float)Nn);
    bnad_kernel<H1><<<Nn/8, 256>>>(pre1, scale, shift, p1Wrel, p1Wroot, rrel1, rroot1, Nn);
    escore_kernel<<<Ee/256, 256>>>(src, tgt, rrel1, sseg1, Ee);
    topk_kernel<NPG, K1><<<Bg, 1024>>>(sseg1, rroot1, p1brel, perm1, tanh1, map1);
    gather_kernel<<<(N1*(H1/4))/256, 256>>>(pre1, perm1, tanh1, h1new, N1);
    remap_kernel<<<Ee/256, 256>>>(src, tgt, map1, src2, tgt2);

    // ---- stage 2 ----
    cudaMemsetAsync(agg2,  0, sizeof(float)*N1*H1);
    cudaMemsetAsync(cnt2,  0, sizeof(float)*N1);
    cudaMemsetAsync(sseg2, 0, sizeof(float)*N1);
    cudaMemsetAsync(bnacc, 0, sizeof(float)*2*H2);

    agg_kernel<H1><<<(Ee*(H1/4))/256, 256>>>(src2, tgt2, h1new, agg2, cnt2, Ee);
    {
        // KD=128, OD=256, BM=64, TN=8, CG=32 ; smem = (32*256 + 32*68)*4 = 41472
        int smem = (32*H2 + 32*(64+4)) * 4;
        gemm_dual2<H1, H2, 64, 8, 32><<<N1/64, 256, smem>>>(agg2, cnt2, h1new, W2l, W2r, b2l, pre2);
    }
    bnstats_kernel<H2><<<256, H2>>>(pre2, bnacc, N1);
    bnfinal_kernel<<<1, H2>>>(bnacc, bn2g, bn2b, scale, shift, H2, 1.f/(float)N1);
    bnad_kernel<H2><<<N1/8, 256>>>(pre2, scale, shift, p2Wrel, p2Wroot, rrel2, rroot2, N1);
    escore_kernel<<<Ee/256, 256>>>(src2, tgt2, rrel2, sseg2, Ee);
    topk_kernel<K1, K2><<<Bg, 1024>>>(sseg2, rroot2, p2brel, perm2, tanh2, nullptr);

    // ---- readout ----
    final_kernel<<<Bg, 256>>>(pre2, perm2, tanh2, Wlin, blin, out);

    (void)in_sizes; (void)n_in; (void)out_size;
}